// round 1
// baseline (speedup 1.0000x reference)
#include <cuda_runtime.h>
#include <cstdint>

// Problem constants: B=2, S=2048, DM=2048, H=16, HD=128
static constexpr int B_   = 2;
static constexpr int S_   = 2048;
static constexpr int DM_  = 2048;
static constexpr int H_   = 16;
static constexpr int HD_  = 128;
static constexpr int M_   = B_ * S_;        // 4096
static constexpr int N3_  = 3 * DM_;        // 6144

// ---------------------------------------------------------------------------
// Scratch (no allocations allowed -> __device__ globals)
// ---------------------------------------------------------------------------
__device__ float g_qkv[(size_t)M_ * N3_];              // [4096, 6144]
__device__ float g_q  [(size_t)B_ * H_ * S_ * HD_];    // [B,H,S,HD]
__device__ float g_k  [(size_t)B_ * H_ * S_ * HD_];
__device__ float g_v  [(size_t)B_ * H_ * S_ * HD_];
__device__ float g_ctx[(size_t)M_ * DM_];              // [B,S,DM] (h-major inside row)

// ---------------------------------------------------------------------------
// SGEMM: C[M,N] = A[M,K] * B[K,N] (+ bias[N]), all row-major, fp32.
// 128x128 block tile, K-tile 16, 256 threads, 8x8 micro-tile per thread.
// ---------------------------------------------------------------------------
__global__ __launch_bounds__(256, 2)
void sgemm_bias_kernel(const float* __restrict__ A, const float* __restrict__ Bm,
                       const float* __restrict__ bias, float* __restrict__ C,
                       int M, int N, int K) {
    __shared__ float As[16 * 132];   // As[k][m], pitch 132 (pad to reduce store conflicts)
    __shared__ float Bs[16 * 128];   // Bs[k][n]

    const int t  = threadIdx.x;
    const int bm = blockIdx.y * 128;
    const int bn = blockIdx.x * 128;
    const int tr = t >> 4;           // 0..15
    const int tc = t & 15;           // 0..15

    float acc[8][8];
#pragma unroll
    for (int i = 0; i < 8; i++)
#pragma unroll
        for (int j = 0; j < 8; j++) acc[i][j] = 0.f;

    // A-tile load mapping: 512 float4 per tile; thread handles f=t and f=t+256.
    const int arow = t >> 2;               // 0..63 (second: +64)
    const int acol = (t & 3) << 2;         // 0,4,8,12
    // B-tile load mapping: rows t>>5 (0..7) and +8, cols (t&31)*4
    const int brow = t >> 5;
    const int bcol = (t & 31) << 2;

    const float* Ap = A  + (size_t)(bm + arow) * K + acol;
    const float* Bp = Bm + (size_t)brow * N + bn + bcol;

    const int nk = K >> 4;
    float4 ra0 = *(const float4*)(Ap);
    float4 ra1 = *(const float4*)(Ap + (size_t)64 * K);
    float4 rb0 = *(const float4*)(Bp);
    float4 rb1 = *(const float4*)(Bp + (size_t)8 * N);

    for (int kt = 0; kt < nk; kt++) {
        // stage to smem
        As[(acol + 0) * 132 + arow] = ra0.x;
        As[(acol + 1) * 132 + arow] = ra0.y;
        As[(acol + 2) * 132 + arow] = ra0.z;
        As[(acol + 3) * 132 + arow] = ra0.w;
        As[(acol + 0) * 132 + arow + 64] = ra1.x;
        As[(acol + 1) * 132 + arow + 64] = ra1.y;
        As[(acol + 2) * 132 + arow + 64] = ra1.z;
        As[(acol + 3) * 132 + arow + 64] = ra1.w;
        *(float4*)(&Bs[brow * 128 + bcol])       = rb0;
        *(float4*)(&Bs[(brow + 8) * 128 + bcol]) = rb1;
        __syncthreads();

        if (kt + 1 < nk) {
            const float* An = Ap + (size_t)(kt + 1) * 16;
            ra0 = *(const float4*)(An);
            ra1 = *(const float4*)(An + (size_t)64 * K);
            const float* Bn = Bp + (size_t)(kt + 1) * 16 * N;
            rb0 = *(const float4*)(Bn);
            rb1 = *(const float4*)(Bn + (size_t)8 * N);
        }

#pragma unroll
        for (int k = 0; k < 16; k++) {
            float av[8], bv[8];
            float4 x;
            x = *(const float4*)(&As[k * 132 + tr * 8]);     av[0]=x.x; av[1]=x.y; av[2]=x.z; av[3]=x.w;
            x = *(const float4*)(&As[k * 132 + tr * 8 + 4]); av[4]=x.x; av[5]=x.y; av[6]=x.z; av[7]=x.w;
            x = *(const float4*)(&Bs[k * 128 + tc * 8]);     bv[0]=x.x; bv[1]=x.y; bv[2]=x.z; bv[3]=x.w;
            x = *(const float4*)(&Bs[k * 128 + tc * 8 + 4]); bv[4]=x.x; bv[5]=x.y; bv[6]=x.z; bv[7]=x.w;
#pragma unroll
            for (int i = 0; i < 8; i++)
#pragma unroll
                for (int j = 0; j < 8; j++)
                    acc[i][j] = fmaf(av[i], bv[j], acc[i][j]);
        }
        __syncthreads();
    }

    // epilogue
    float bj[8];
#pragma unroll
    for (int j = 0; j < 8; j++) bj[j] = bias ? bias[bn + tc * 8 + j] : 0.f;

#pragma unroll
    for (int i = 0; i < 8; i++) {
        const size_t row = (size_t)(bm + tr * 8 + i);
        float* Cp = C + row * N + bn + tc * 8;
        float4 o0, o1;
        o0.x = acc[i][0] + bj[0]; o0.y = acc[i][1] + bj[1];
        o0.z = acc[i][2] + bj[2]; o0.w = acc[i][3] + bj[3];
        o1.x = acc[i][4] + bj[4]; o1.y = acc[i][5] + bj[5];
        o1.z = acc[i][6] + bj[6]; o1.w = acc[i][7] + bj[7];
        *(float4*)(Cp)     = o0;
        *(float4*)(Cp + 4) = o1;
    }
}

// ---------------------------------------------------------------------------
// RoPE + scatter: qkv[4096,6144] -> q,k,v in [B,H,S,HD] layout.
// rot == HD (cos has 128 cols), so the whole head dim is rotated.
// ---------------------------------------------------------------------------
__global__ void rope_kernel(const float* __restrict__ qkv,
                            const float* __restrict__ cosb,
                            const float* __restrict__ sinb,
                            float* __restrict__ q, float* __restrict__ k,
                            float* __restrict__ v) {
    const int idx = blockIdx.x * blockDim.x + threadIdx.x;   // < 2^23
    const int d = idx & 127;
    const int h = (idx >> 7) & 15;
    const int s = (idx >> 11) & 2047;
    const int b = idx >> 22;

    const float* row = qkv + (size_t)(b * S_ + s) * N3_;
    const float c  = cosb[s * HD_ + d];
    const float sn = sinb[s * HD_ + d];
    const int col   = h * HD_ + d;
    const int paird = (d < 64) ? d + 64 : d - 64;
    const float sgn = (d < 64) ? -1.f : 1.f;

    const float qv = row[col];
    const float qp = row[h * HD_ + paird];
    const float kv = row[DM_ + col];
    const float kp = row[DM_ + h * HD_ + paird];

    const size_t o = ((size_t)((b * H_ + h) * S_ + s)) * HD_ + d;
    q[o] = fmaf(qv, c, sgn * qp * sn);
    k[o] = fmaf(kv, c, sgn * kp * sn);
    v[o] = row[2 * DM_ + col];
}

// ---------------------------------------------------------------------------
// Causal flash attention.
// One block per (qt, bh): 64 q rows, loop over K tiles of 64 rows (kt <= qt).
// Dynamic smem: Qt[128][68] (transposed) | Kt[128][68] (transposed; reused as
// Ps[64][68]) | Vs[64][128]. 256 threads. Score micro-tile 4x4 (16x16 grid),
// PV micro-tile 4x8.
// ---------------------------------------------------------------------------
static constexpr int QT_PITCH = 68;
static constexpr int FLASH_SMEM_FLOATS = 128 * QT_PITCH * 2 + 64 * 128; // 25600
static constexpr int FLASH_SMEM_BYTES  = FLASH_SMEM_FLOATS * 4;         // 102400

__global__ __launch_bounds__(256)
void flash_kernel(const float* __restrict__ Q, const float* __restrict__ K,
                  const float* __restrict__ V, float* __restrict__ Ctx) {
    extern __shared__ float sm[];
    float* Qt = sm;                      // [128][68]
    float* Kt = sm + 128 * QT_PITCH;     // [128][68]  (reused as Ps[64][68])
    float* Vs = sm + 2 * 128 * QT_PITCH; // [64][128]

    const int t  = threadIdx.x;
    const int tr = t >> 4;   // 0..15  (rows tr*4 .. tr*4+3)
    const int tc = t & 15;   // 0..15
    const int qt = blockIdx.x;
    const int bh = blockIdx.y;

    const float* Qp = Q + (size_t)bh * S_ * HD_;
    const float* Kp = K + (size_t)bh * S_ * HD_;
    const float* Vp = V + (size_t)bh * S_ * HD_;
    const int q0 = qt * 64;

    // load Q tile transposed: Qt[d][i]
    for (int f = t; f < 64 * 32; f += 256) {
        const int i  = f >> 5;
        const int d0 = (f & 31) << 2;
        const float4 vq = *(const float4*)(Qp + (size_t)(q0 + i) * HD_ + d0);
        Qt[(d0 + 0) * QT_PITCH + i] = vq.x;
        Qt[(d0 + 1) * QT_PITCH + i] = vq.y;
        Qt[(d0 + 2) * QT_PITCH + i] = vq.z;
        Qt[(d0 + 3) * QT_PITCH + i] = vq.w;
    }

    float m_i[4], l_i[4], outacc[4][8];
#pragma unroll
    for (int i = 0; i < 4; i++) {
        m_i[i] = -1e30f; l_i[i] = 0.f;
#pragma unroll
        for (int j = 0; j < 8; j++) outacc[i][j] = 0.f;
    }
    const float scale = 0.08838834764831845f;   // 1/sqrt(128)

    for (int kt = 0; kt <= qt; kt++) {
        const int k0 = kt * 64;
        __syncthreads();   // previous PV (Ps/Vs reads) done before overwrite

        // load K tile transposed + V tile direct
        for (int f = t; f < 64 * 32; f += 256) {
            const int j  = f >> 5;
            const int d0 = (f & 31) << 2;
            const float4 vk = *(const float4*)(Kp + (size_t)(k0 + j) * HD_ + d0);
            Kt[(d0 + 0) * QT_PITCH + j] = vk.x;
            Kt[(d0 + 1) * QT_PITCH + j] = vk.y;
            Kt[(d0 + 2) * QT_PITCH + j] = vk.z;
            Kt[(d0 + 3) * QT_PITCH + j] = vk.w;
            *(float4*)(&Vs[j * 128 + d0]) = *(const float4*)(Vp + (size_t)(k0 + j) * HD_ + d0);
        }
        __syncthreads();

        // scores: sc[i][j] = sum_d Qt[d][tr*4+i] * Kt[d][tc*4+j]
        float sc[4][4];
#pragma unroll
        for (int i = 0; i < 4; i++)
#pragma unroll
            for (int j = 0; j < 4; j++) sc[i][j] = 0.f;

#pragma unroll 4
        for (int d = 0; d < 128; d++) {
            const float4 a  = *(const float4*)(&Qt[d * QT_PITCH + tr * 4]);
            const float4 bb = *(const float4*)(&Kt[d * QT_PITCH + tc * 4]);
            const float av[4] = {a.x, a.y, a.z, a.w};
            const float bv[4] = {bb.x, bb.y, bb.z, bb.w};
#pragma unroll
            for (int i = 0; i < 4; i++)
#pragma unroll
                for (int j = 0; j < 4; j++)
                    sc[i][j] = fmaf(av[i], bv[j], sc[i][j]);
        }

        // scale + causal mask (only on the diagonal tile)
#pragma unroll
        for (int i = 0; i < 4; i++)
#pragma unroll
            for (int j = 0; j < 4; j++) {
                sc[i][j] *= scale;
                if (kt == qt && (tc * 4 + j) > (tr * 4 + i)) sc[i][j] = -1e30f;
            }

        // online softmax (rows owned by the 16 threads sharing tr)
#pragma unroll
        for (int i = 0; i < 4; i++) {
            float rm = fmaxf(fmaxf(sc[i][0], sc[i][1]), fmaxf(sc[i][2], sc[i][3]));
            rm = fmaxf(rm, __shfl_xor_sync(0xffffffffu, rm, 1));
            rm = fmaxf(rm, __shfl_xor_sync(0xffffffffu, rm, 2));
            rm = fmaxf(rm, __shfl_xor_sync(0xffffffffu, rm, 4));
            rm = fmaxf(rm, __shfl_xor_sync(0xffffffffu, rm, 8));
            const float mn   = fmaxf(m_i[i], rm);
            const float corr = __expf(m_i[i] - mn);
            float rs = 0.f;
#pragma unroll
            for (int j = 0; j < 4; j++) {
                sc[i][j] = __expf(sc[i][j] - mn);
                rs += sc[i][j];
            }
            rs += __shfl_xor_sync(0xffffffffu, rs, 1);
            rs += __shfl_xor_sync(0xffffffffu, rs, 2);
            rs += __shfl_xor_sync(0xffffffffu, rs, 4);
            rs += __shfl_xor_sync(0xffffffffu, rs, 8);
            l_i[i] = l_i[i] * corr + rs;
            m_i[i] = mn;
#pragma unroll
            for (int jd = 0; jd < 8; jd++) outacc[i][jd] *= corr;
        }

        __syncthreads();   // all threads done reading Kt before Ps overwrite
        float* Ps = Kt;    // [64][68]
#pragma unroll
        for (int i = 0; i < 4; i++)
            *(float4*)(&Ps[(tr * 4 + i) * QT_PITCH + tc * 4]) =
                make_float4(sc[i][0], sc[i][1], sc[i][2], sc[i][3]);
        __syncthreads();

        // PV: outacc[i][jd] += sum_j Ps[tr*4+i][j] * Vs[j][tc*8+jd]
#pragma unroll 4
        for (int j = 0; j < 64; j++) {
            float a[4];
#pragma unroll
            for (int i = 0; i < 4; i++) a[i] = Ps[(tr * 4 + i) * QT_PITCH + j];
            const float4 v0 = *(const float4*)(&Vs[j * 128 + tc * 8]);
            const float4 v1 = *(const float4*)(&Vs[j * 128 + tc * 8 + 4]);
            const float vv[8] = {v0.x, v0.y, v0.z, v0.w, v1.x, v1.y, v1.z, v1.w};
#pragma unroll
            for (int i = 0; i < 4; i++)
#pragma unroll
                for (int jd = 0; jd < 8; jd++)
                    outacc[i][jd] = fmaf(a[i], vv[jd], outacc[i][jd]);
        }
    }

    // epilogue: normalize and write ctx[b, s, h*128 + dcol]
    const int b = bh >> 4;
    const int h = bh & 15;
#pragma unroll
    for (int i = 0; i < 4; i++) {
        const int srow = q0 + tr * 4 + i;
        const float inv = 1.f / l_i[i];
        float* Cp = Ctx + ((size_t)(b * S_ + srow)) * DM_ + h * HD_ + tc * 8;
        float4 o0, o1;
        o0.x = outacc[i][0] * inv; o0.y = outacc[i][1] * inv;
        o0.z = outacc[i][2] * inv; o0.w = outacc[i][3] * inv;
        o1.x = outacc[i][4] * inv; o1.y = outacc[i][5] * inv;
        o1.z = outacc[i][6] * inv; o1.w = outacc[i][7] * inv;
        *(float4*)(Cp)     = o0;
        *(float4*)(Cp + 4) = o1;
    }
}

// ---------------------------------------------------------------------------
// Launch orchestration
// ---------------------------------------------------------------------------
extern "C" void kernel_launch(void* const* d_in, const int* in_sizes, int n_in,
                              void* d_out, int out_size) {
    const float* hs     = (const float*)d_in[0];  // [B,S,DM]
    const float* cosb   = (const float*)d_in[1];  // [1,S,1,HD]
    const float* sinb   = (const float*)d_in[2];
    const float* w_attn = (const float*)d_in[3];  // [DM, 3DM]
    const float* b_attn = (const float*)d_in[4];  // [3DM]
    const float* w_proj = (const float*)d_in[5];  // [DM, DM]
    float* out = (float*)d_out;

    float *qkv, *q, *k, *v, *ctx;
    cudaGetSymbolAddress((void**)&qkv, g_qkv);
    cudaGetSymbolAddress((void**)&q,   g_q);
    cudaGetSymbolAddress((void**)&k,   g_k);
    cudaGetSymbolAddress((void**)&v,   g_v);
    cudaGetSymbolAddress((void**)&ctx, g_ctx);

    // 1) QKV GEMM + bias
    {
        dim3 grid(N3_ / 128, M_ / 128);
        sgemm_bias_kernel<<<grid, 256>>>(hs, w_attn, b_attn, qkv, M_, N3_, DM_);
    }
    // 2) RoPE + scatter to [B,H,S,HD]
    {
        const int total = B_ * S_ * H_ * HD_;   // 2^23
        rope_kernel<<<total / 256, 256>>>(qkv, cosb, sinb, q, k, v);
    }
    // 3) Causal flash attention -> ctx [B,S,DM]
    {
        cudaFuncSetAttribute(flash_kernel,
                             cudaFuncAttributeMaxDynamicSharedMemorySize,
                             FLASH_SMEM_BYTES);
        dim3 grid(S_ / 64, B_ * H_);
        flash_kernel<<<grid, 256, FLASH_SMEM_BYTES>>>(q, k, v, ctx);
    }
    // 4) Projection GEMM
    {
        dim3 grid(DM_ / 128, M_ / 128);
        sgemm_bias_kernel<<<grid, 256>>>(ctx, w_proj, nullptr, out, M_, DM_, DM_);
    }
}

// round 2
// speedup vs baseline: 2.0550x; 2.0550x over previous
#include <cuda_runtime.h>
#include <cstdint>

// Problem constants: B=2, S=2048, DM=2048, H=16, HD=128
static constexpr int B_   = 2;
static constexpr int S_   = 2048;
static constexpr int DM_  = 2048;
static constexpr int H_   = 16;
static constexpr int HD_  = 128;
static constexpr int M_   = B_ * S_;        // 4096
static constexpr int N3_  = 3 * DM_;        // 6144

// ---------------------------------------------------------------------------
// Scratch (no allocations allowed -> __device__ globals)
// ---------------------------------------------------------------------------
__device__ float g_qkv[(size_t)M_ * N3_];              // [4096, 6144]
__device__ float g_q  [(size_t)B_ * H_ * S_ * HD_];    // [B,H,S,HD]
__device__ float g_k  [(size_t)B_ * H_ * S_ * HD_];
__device__ float g_v  [(size_t)B_ * H_ * S_ * HD_];
__device__ float g_ctx[(size_t)M_ * DM_];              // [B,S,DM]

// ---------------------------------------------------------------------------
// tf32 helpers
// ---------------------------------------------------------------------------
__device__ __forceinline__ uint32_t f2tf(float x) {
    uint32_t u;
    asm("cvt.rna.tf32.f32 %0, %1;" : "=r"(u) : "f"(x));
    return u;
}

__device__ __forceinline__ void mma8(float* c,
                                     uint32_t a0, uint32_t a1, uint32_t a2, uint32_t a3,
                                     uint32_t b0, uint32_t b1) {
    asm volatile(
        "mma.sync.aligned.m16n8k8.row.col.f32.tf32.tf32.f32 "
        "{%0,%1,%2,%3},{%4,%5,%6,%7},{%8,%9},{%0,%1,%2,%3};"
        : "+f"(c[0]), "+f"(c[1]), "+f"(c[2]), "+f"(c[3])
        : "r"(a0), "r"(a1), "r"(a2), "r"(a3), "r"(b0), "r"(b1));
}

// ---------------------------------------------------------------------------
// tf32 GEMM: C[M,N] = A[M,K] * B[K,N] (+ bias[N]), row-major fp32 in/out.
// 128x128 block tile, K-tile 16, 256 threads (8 warps, 2x4), warp tile 64x32,
// per-warp 4x4 grid of m16n8k8 mma. Smem pitch 136 (== 8 mod 32) makes all
// fragment loads bank-conflict-free.
// ---------------------------------------------------------------------------
__global__ __launch_bounds__(256, 1)
void gemm_tf32(const float* __restrict__ A, const float* __restrict__ Bm,
               const float* __restrict__ bias, float* __restrict__ C,
               int M, int N, int K) {
    __shared__ uint32_t As[16 * 136];   // As[k][m]
    __shared__ uint32_t Bs[16 * 136];   // Bs[k][n]

    const int t    = threadIdx.x;
    const int lane = t & 31;
    const int wid  = t >> 5;
    const int g    = lane >> 2;
    const int l4   = lane & 3;
    const int wm   = (wid & 1) * 64;
    const int wn   = (wid >> 1) * 32;
    const int bm   = blockIdx.y * 128;
    const int bn   = blockIdx.x * 128;

    float acc[4][4][4];
#pragma unroll
    for (int mt = 0; mt < 4; mt++)
#pragma unroll
        for (int nt = 0; nt < 4; nt++)
#pragma unroll
            for (int e = 0; e < 4; e++) acc[mt][nt][e] = 0.f;

    const int arow = t >> 2;               // 0..63 (+64 for second half)
    const int acol = (t & 3) << 2;         // 0,4,8,12
    const int brow = t >> 5;               // 0..7 (+8)
    const int bcol = (t & 31) << 2;

    const float* Ap = A  + (size_t)(bm + arow) * K + acol;
    const float* Bp = Bm + (size_t)brow * N + bn + bcol;

    const int nk = K >> 4;
    float4 ra0 = *(const float4*)(Ap);
    float4 ra1 = *(const float4*)(Ap + (size_t)64 * K);
    float4 rb0 = *(const float4*)(Bp);
    float4 rb1 = *(const float4*)(Bp + (size_t)8 * N);

    for (int kt = 0; kt < nk; kt++) {
        // stage (convert to tf32)
        As[(acol + 0) * 136 + arow] = f2tf(ra0.x);
        As[(acol + 1) * 136 + arow] = f2tf(ra0.y);
        As[(acol + 2) * 136 + arow] = f2tf(ra0.z);
        As[(acol + 3) * 136 + arow] = f2tf(ra0.w);
        As[(acol + 0) * 136 + arow + 64] = f2tf(ra1.x);
        As[(acol + 1) * 136 + arow + 64] = f2tf(ra1.y);
        As[(acol + 2) * 136 + arow + 64] = f2tf(ra1.z);
        As[(acol + 3) * 136 + arow + 64] = f2tf(ra1.w);
        {
            uint4 u0 = make_uint4(f2tf(rb0.x), f2tf(rb0.y), f2tf(rb0.z), f2tf(rb0.w));
            uint4 u1 = make_uint4(f2tf(rb1.x), f2tf(rb1.y), f2tf(rb1.z), f2tf(rb1.w));
            *(uint4*)(&Bs[brow * 136 + bcol])       = u0;
            *(uint4*)(&Bs[(brow + 8) * 136 + bcol]) = u1;
        }
        __syncthreads();

        if (kt + 1 < nk) {
            const float* An = Ap + (size_t)(kt + 1) * 16;
            ra0 = *(const float4*)(An);
            ra1 = *(const float4*)(An + (size_t)64 * K);
            const float* Bn = Bp + (size_t)(kt + 1) * 16 * N;
            rb0 = *(const float4*)(Bn);
            rb1 = *(const float4*)(Bn + (size_t)8 * N);
        }

#pragma unroll
        for (int ks = 0; ks < 2; ks++) {
            const int k0 = ks * 8;
            uint32_t af[4][4], bf[4][2];
#pragma unroll
            for (int mt = 0; mt < 4; mt++) {
                const int base = (k0 + l4) * 136 + wm + mt * 16 + g;
                af[mt][0] = As[base];
                af[mt][1] = As[base + 8];
                af[mt][2] = As[base + 4 * 136];
                af[mt][3] = As[base + 4 * 136 + 8];
            }
#pragma unroll
            for (int nt = 0; nt < 4; nt++) {
                const int base = (k0 + l4) * 136 + wn + nt * 8 + g;
                bf[nt][0] = Bs[base];
                bf[nt][1] = Bs[base + 4 * 136];
            }
#pragma unroll
            for (int mt = 0; mt < 4; mt++)
#pragma unroll
                for (int nt = 0; nt < 4; nt++)
                    mma8(acc[mt][nt], af[mt][0], af[mt][1], af[mt][2], af[mt][3],
                         bf[nt][0], bf[nt][1]);
        }
        __syncthreads();
    }

    // epilogue
#pragma unroll
    for (int mt = 0; mt < 4; mt++) {
#pragma unroll
        for (int nt = 0; nt < 4; nt++) {
            const int row = bm + wm + mt * 16 + g;
            const int col = bn + wn + nt * 8 + l4 * 2;
            float b0 = bias ? bias[col]     : 0.f;
            float b1 = bias ? bias[col + 1] : 0.f;
            float2 o0 = make_float2(acc[mt][nt][0] + b0, acc[mt][nt][1] + b1);
            float2 o1 = make_float2(acc[mt][nt][2] + b0, acc[mt][nt][3] + b1);
            *(float2*)(C + (size_t)row * N + col)       = o0;
            *(float2*)(C + (size_t)(row + 8) * N + col) = o1;
        }
    }
}

// ---------------------------------------------------------------------------
// RoPE + scatter: qkv[4096,6144] -> q,k,v in [B,H,S,HD] layout.
// ---------------------------------------------------------------------------
__global__ void rope_kernel(const float* __restrict__ qkv,
                            const float* __restrict__ cosb,
                            const float* __restrict__ sinb,
                            float* __restrict__ q, float* __restrict__ k,
                            float* __restrict__ v) {
    const int idx = blockIdx.x * blockDim.x + threadIdx.x;
    const int d = idx & 127;
    const int h = (idx >> 7) & 15;
    const int s = (idx >> 11) & 2047;
    const int b = idx >> 22;

    const float* row = qkv + (size_t)(b * S_ + s) * N3_;
    const float c  = cosb[s * HD_ + d];
    const float sn = sinb[s * HD_ + d];
    const int col   = h * HD_ + d;
    const int paird = (d < 64) ? d + 64 : d - 64;
    const float sgn = (d < 64) ? -1.f : 1.f;

    const float qv = row[col];
    const float qp = row[h * HD_ + paird];
    const float kv = row[DM_ + col];
    const float kp = row[DM_ + h * HD_ + paird];

    const size_t o = ((size_t)((b * H_ + h) * S_ + s)) * HD_ + d;
    q[o] = fmaf(qv, c, sgn * qp * sn);
    k[o] = fmaf(kv, c, sgn * kp * sn);
    v[o] = row[2 * DM_ + col];
}

// ---------------------------------------------------------------------------
// Causal flash attention with tf32 mma.
// Block: 128 q-rows x one (b,h). 256 threads = 8 warps; warp owns 16 q-rows.
// K-tile Bk=64. S warp tile 16x64 (8 n-tiles), O warp tile 16x128 (16 n-tiles).
// Smem (tf32 as uint32): Qs[d=128][m=128 p136], Ks[d=128][j=64 p72],
// Vs[j=64][d=128 p136], Ps[j=64][m=128 p136]. All pitches == 8 mod 32 =>
// conflict-free fragment access. Total 176128 B.
// ---------------------------------------------------------------------------
static constexpr int QS_OFF = 0;                       // 128*136 = 17408
static constexpr int KS_OFF = QS_OFF + 128 * 136;      // 128*72  = 9216
static constexpr int VS_OFF = KS_OFF + 128 * 72;       // 64*136  = 8704
static constexpr int PS_OFF = VS_OFF + 64 * 136;       // 64*136  = 8704
static constexpr int FL_SMEM_U32 = PS_OFF + 64 * 136;  // 44032
static constexpr int FL_SMEM_BYTES = FL_SMEM_U32 * 4;  // 176128

__global__ __launch_bounds__(256, 1)
void flash_tf32(const float* __restrict__ Q, const float* __restrict__ K,
                const float* __restrict__ V, float* __restrict__ Ctx) {
    extern __shared__ uint32_t sm[];
    uint32_t* Qs = sm + QS_OFF;
    uint32_t* Ks = sm + KS_OFF;
    uint32_t* Vs = sm + VS_OFF;
    uint32_t* Ps = sm + PS_OFF;

    const int t    = threadIdx.x;
    const int lane = t & 31;
    const int wid  = t >> 5;
    const int g    = lane >> 2;
    const int l4   = lane & 3;
    const int mrow = wid * 16;

    const int qt = gridDim.x - 1 - blockIdx.x;   // heavy tiles scheduled first
    const int bh = blockIdx.y;
    const int q0 = qt * 128;

    const float* Qp = Q + (size_t)bh * S_ * HD_;
    const float* Kp = K + (size_t)bh * S_ * HD_;
    const float* Vp = V + (size_t)bh * S_ * HD_;

    // load Q tile transposed: Qs[d][m] (tf32)
    for (int f = t; f < 128 * 32; f += 256) {
        const int r  = f >> 5;
        const int d0 = (f & 31) << 2;
        const float4 vq = *(const float4*)(Qp + (size_t)(q0 + r) * HD_ + d0);
        Qs[(d0 + 0) * 136 + r] = f2tf(vq.x);
        Qs[(d0 + 1) * 136 + r] = f2tf(vq.y);
        Qs[(d0 + 2) * 136 + r] = f2tf(vq.z);
        Qs[(d0 + 3) * 136 + r] = f2tf(vq.w);
    }

    float o[16][4];
#pragma unroll
    for (int nt = 0; nt < 16; nt++)
#pragma unroll
        for (int e = 0; e < 4; e++) o[nt][e] = 0.f;
    float m0 = -1e30f, m1 = -1e30f, li0 = 0.f, li1 = 0.f;
    const float scale = 0.08838834764831845f;   // 1/sqrt(128)

    const int nkt = 2 * qt + 2;
    for (int kt = 0; kt < nkt; kt++) {
        const int k0g = kt * 64;
        __syncthreads();   // prior PV done reading Vs/Ps; prior S done with Ks

        // load K tile transposed (Ks[d][j]) + V tile direct (Vs[j][d]), tf32
        for (int f = t; f < 64 * 32; f += 256) {
            const int j  = f >> 5;
            const int d0 = (f & 31) << 2;
            const float4 vk = *(const float4*)(Kp + (size_t)(k0g + j) * HD_ + d0);
            Ks[(d0 + 0) * 72 + j] = f2tf(vk.x);
            Ks[(d0 + 1) * 72 + j] = f2tf(vk.y);
            Ks[(d0 + 2) * 72 + j] = f2tf(vk.z);
            Ks[(d0 + 3) * 72 + j] = f2tf(vk.w);
            const float4 vv = *(const float4*)(Vp + (size_t)(k0g + j) * HD_ + d0);
            *(uint4*)(&Vs[j * 136 + d0]) =
                make_uint4(f2tf(vv.x), f2tf(vv.y), f2tf(vv.z), f2tf(vv.w));
        }
        __syncthreads();

        // S = Q K^T : warp computes rows [mrow,mrow+16) x 64 cols
        float sc[8][4];
#pragma unroll
        for (int nt = 0; nt < 8; nt++)
#pragma unroll
            for (int e = 0; e < 4; e++) sc[nt][e] = 0.f;

#pragma unroll
        for (int ks = 0; ks < 16; ks++) {
            const int k0 = ks * 8;
            const int ab = (k0 + l4) * 136 + mrow + g;
            uint32_t a0 = Qs[ab], a1 = Qs[ab + 8];
            uint32_t a2 = Qs[ab + 4 * 136], a3 = Qs[ab + 4 * 136 + 8];
#pragma unroll
            for (int nt = 0; nt < 8; nt++) {
                const int bb = (k0 + l4) * 72 + nt * 8 + g;
                mma8(sc[nt], a0, a1, a2, a3, Ks[bb], Ks[bb + 4 * 72]);
            }
        }

        // scale + causal mask (only last two tiles can cross the diagonal)
        const bool need_mask = (kt >= 2 * qt);
        const int row0 = q0 + mrow + g;
        const int row1 = row0 + 8;
#pragma unroll
        for (int nt = 0; nt < 8; nt++) {
            const int col = k0g + nt * 8 + l4 * 2;
#pragma unroll
            for (int e = 0; e < 4; e++) sc[nt][e] *= scale;
            if (need_mask) {
                if (col     > row0) sc[nt][0] = -1e30f;
                if (col + 1 > row0) sc[nt][1] = -1e30f;
                if (col     > row1) sc[nt][2] = -1e30f;
                if (col + 1 > row1) sc[nt][3] = -1e30f;
            }
        }

        // online softmax: rows row0 (regs 0,1) and row1 (regs 2,3)
        float rm0 = -1e30f, rm1 = -1e30f;
#pragma unroll
        for (int nt = 0; nt < 8; nt++) {
            rm0 = fmaxf(rm0, fmaxf(sc[nt][0], sc[nt][1]));
            rm1 = fmaxf(rm1, fmaxf(sc[nt][2], sc[nt][3]));
        }
        rm0 = fmaxf(rm0, __shfl_xor_sync(0xffffffffu, rm0, 1));
        rm0 = fmaxf(rm0, __shfl_xor_sync(0xffffffffu, rm0, 2));
        rm1 = fmaxf(rm1, __shfl_xor_sync(0xffffffffu, rm1, 1));
        rm1 = fmaxf(rm1, __shfl_xor_sync(0xffffffffu, rm1, 2));

        const float mn0 = fmaxf(m0, rm0), mn1 = fmaxf(m1, rm1);
        const float corr0 = __expf(m0 - mn0), corr1 = __expf(m1 - mn1);
        float rs0 = 0.f, rs1 = 0.f;
#pragma unroll
        for (int nt = 0; nt < 8; nt++) {
            sc[nt][0] = __expf(sc[nt][0] - mn0);
            sc[nt][1] = __expf(sc[nt][1] - mn0);
            sc[nt][2] = __expf(sc[nt][2] - mn1);
            sc[nt][3] = __expf(sc[nt][3] - mn1);
            rs0 += sc[nt][0] + sc[nt][1];
            rs1 += sc[nt][2] + sc[nt][3];
        }
        rs0 += __shfl_xor_sync(0xffffffffu, rs0, 1);
        rs0 += __shfl_xor_sync(0xffffffffu, rs0, 2);
        rs1 += __shfl_xor_sync(0xffffffffu, rs1, 1);
        rs1 += __shfl_xor_sync(0xffffffffu, rs1, 2);
        li0 = li0 * corr0 + rs0; m0 = mn0;
        li1 = li1 * corr1 + rs1; m1 = mn1;
#pragma unroll
        for (int nt = 0; nt < 16; nt++) {
            o[nt][0] *= corr0; o[nt][1] *= corr0;
            o[nt][2] *= corr1; o[nt][3] *= corr1;
        }

        // write P transposed: Ps[j][m] (tf32)
#pragma unroll
        for (int nt = 0; nt < 8; nt++) {
            const int cb = nt * 8 + l4 * 2;
            Ps[cb * 136       + mrow + g]     = f2tf(sc[nt][0]);
            Ps[(cb + 1) * 136 + mrow + g]     = f2tf(sc[nt][1]);
            Ps[cb * 136       + mrow + g + 8] = f2tf(sc[nt][2]);
            Ps[(cb + 1) * 136 + mrow + g + 8] = f2tf(sc[nt][3]);
        }
        __syncthreads();   // all P written before PV reads

        // O += P V : warp rows [mrow,mrow+16) x 128 d-cols
#pragma unroll
        for (int ks = 0; ks < 8; ks++) {
            const int k0 = ks * 8;
            const int ab = (k0 + l4) * 136 + mrow + g;
            uint32_t a0 = Ps[ab], a1 = Ps[ab + 8];
            uint32_t a2 = Ps[ab + 4 * 136], a3 = Ps[ab + 4 * 136 + 8];
#pragma unroll
            for (int nt = 0; nt < 16; nt++) {
                const int bb = (k0 + l4) * 136 + nt * 8 + g;
                mma8(o[nt], a0, a1, a2, a3, Vs[bb], Vs[bb + 4 * 136]);
            }
        }
    }

    // epilogue: normalize and write ctx[b, s, h*128 + d]
    const int b = bh >> 4;
    const int h = bh & 15;
    const float inv0 = 1.f / li0, inv1 = 1.f / li1;
    const int r0 = q0 + mrow + g;
#pragma unroll
    for (int nt = 0; nt < 16; nt++) {
        const int col = h * HD_ + nt * 8 + l4 * 2;
        *(float2*)(Ctx + (size_t)(b * S_ + r0) * DM_ + col) =
            make_float2(o[nt][0] * inv0, o[nt][1] * inv0);
        *(float2*)(Ctx + (size_t)(b * S_ + r0 + 8) * DM_ + col) =
            make_float2(o[nt][2] * inv1, o[nt][3] * inv1);
    }
}

// ---------------------------------------------------------------------------
// Launch orchestration
// ---------------------------------------------------------------------------
extern "C" void kernel_launch(void* const* d_in, const int* in_sizes, int n_in,
                              void* d_out, int out_size) {
    const float* hs     = (const float*)d_in[0];
    const float* cosb   = (const float*)d_in[1];
    const float* sinb   = (const float*)d_in[2];
    const float* w_attn = (const float*)d_in[3];
    const float* b_attn = (const float*)d_in[4];
    const float* w_proj = (const float*)d_in[5];
    float* out = (float*)d_out;

    float *qkv, *q, *k, *v, *ctx;
    cudaGetSymbolAddress((void**)&qkv, g_qkv);
    cudaGetSymbolAddress((void**)&q,   g_q);
    cudaGetSymbolAddress((void**)&k,   g_k);
    cudaGetSymbolAddress((void**)&v,   g_v);
    cudaGetSymbolAddress((void**)&ctx, g_ctx);

    // 1) QKV GEMM + bias (tf32 tensor cores)
    {
        dim3 grid(N3_ / 128, M_ / 128);
        gemm_tf32<<<grid, 256>>>(hs, w_attn, b_attn, qkv, M_, N3_, DM_);
    }
    // 2) RoPE + scatter
    {
        const int total = B_ * S_ * H_ * HD_;
        rope_kernel<<<total / 256, 256>>>(qkv, cosb, sinb, q, k, v);
    }
    // 3) Causal flash attention (tf32 tensor cores)
    {
        cudaFuncSetAttribute(flash_tf32,
                             cudaFuncAttributeMaxDynamicSharedMemorySize,
                             FL_SMEM_BYTES);
        dim3 grid(S_ / 128, B_ * H_);
        flash_tf32<<<grid, 256, FL_SMEM_BYTES>>>(q, k, v, ctx);
    }
    // 4) Projection GEMM (tf32 tensor cores)
    {
        dim3 grid(DM_ / 128, M_ / 128);
        gemm_tf32<<<grid, 256>>>(ctx, w_proj, nullptr, out, M_, DM_, DM_);
    }
}

// round 3
// speedup vs baseline: 2.7687x; 1.3473x over previous
#include <cuda_runtime.h>
#include <cstdint>

// Problem constants: B=2, S=2048, DM=2048, H=16, HD=128
static constexpr int B_   = 2;
static constexpr int S_   = 2048;
static constexpr int DM_  = 2048;
static constexpr int H_   = 16;
static constexpr int HD_  = 128;
static constexpr int M_   = B_ * S_;        // 4096
static constexpr int N3_  = 3 * DM_;        // 6144

// ---------------------------------------------------------------------------
// Scratch (no allocations allowed -> __device__ globals)
// ---------------------------------------------------------------------------
__device__ float g_qkv[(size_t)M_ * N3_];              // [4096, 6144] fp32
__device__ float g_q  [(size_t)B_ * H_ * S_ * HD_];    // [B,H,S,HD] tf32-rounded
__device__ float g_k  [(size_t)B_ * H_ * S_ * HD_];
__device__ float g_v  [(size_t)B_ * H_ * S_ * HD_];
__device__ float g_ctx[(size_t)M_ * DM_];              // [B,S,DM] tf32-rounded
__device__ float g_hsr[(size_t)M_ * DM_];              // tf32-rounded hs
__device__ float g_war[(size_t)DM_ * N3_];             // tf32-rounded w_attn
__device__ float g_wpr[(size_t)DM_ * DM_];             // tf32-rounded w_proj

// ---------------------------------------------------------------------------
// tf32 helpers
// ---------------------------------------------------------------------------
__device__ __forceinline__ uint32_t f2tf(float x) {
    uint32_t u;
    asm("cvt.rna.tf32.f32 %0, %1;" : "=r"(u) : "f"(x));
    return u;
}

__device__ __forceinline__ void mma8(float* c,
                                     uint32_t a0, uint32_t a1, uint32_t a2, uint32_t a3,
                                     uint32_t b0, uint32_t b1) {
    asm volatile(
        "mma.sync.aligned.m16n8k8.row.col.f32.tf32.tf32.f32 "
        "{%0,%1,%2,%3},{%4,%5,%6,%7},{%8,%9},{%0,%1,%2,%3};"
        : "+f"(c[0]), "+f"(c[1]), "+f"(c[2]), "+f"(c[3])
        : "r"(a0), "r"(a1), "r"(a2), "r"(a3), "r"(b0), "r"(b1));
}

__device__ __forceinline__ void cp16(uint32_t dst_smem, const void* src) {
    asm volatile("cp.async.cg.shared.global [%0], [%1], 16;"
                 :: "r"(dst_smem), "l"(src));
}
__device__ __forceinline__ void cp_commit() {
    asm volatile("cp.async.commit_group;");
}
template <int N>
__device__ __forceinline__ void cp_wait() {
    asm volatile("cp.async.wait_group %0;" :: "n"(N));
}

// ---------------------------------------------------------------------------
// Prep: round fp32 arrays to tf32 (rna) so GEMMs can cp.async raw bytes.
// ---------------------------------------------------------------------------
__global__ void round4_kernel(const float* __restrict__ in,
                              float* __restrict__ out, int n4) {
    int i = blockIdx.x * blockDim.x + threadIdx.x;
    if (i >= n4) return;
    float4 v = ((const float4*)in)[i];
    ((uint4*)out)[i] = make_uint4(f2tf(v.x), f2tf(v.y), f2tf(v.z), f2tf(v.w));
}

// ---------------------------------------------------------------------------
// tf32 GEMM with cp.async double buffering.
// Inputs A,B are PRE-ROUNDED to tf32. C fp32 (+bias).
// 128x128 block tile, K-tile 16, 256 threads (8 warps 2x4), warp 64x32.
// Smem raw layouts: As[m=128][k=16 pitch20], Bs[k=16][n=128 pitch136].
// ---------------------------------------------------------------------------
static constexpr int GA_ST = 128 * 20;   // 2560 u32 per A stage
static constexpr int GB_ST = 16 * 136;   // 2176 u32 per B stage

__global__ __launch_bounds__(256, 1)
void gemm_tf32(const float* __restrict__ A, const float* __restrict__ Bm,
               const float* __restrict__ bias, float* __restrict__ C,
               int M, int N, int K) {
    __shared__ uint32_t As[2 * GA_ST];
    __shared__ uint32_t Bs[2 * GB_ST];

    const int t    = threadIdx.x;
    const int lane = t & 31;
    const int wid  = t >> 5;
    const int g    = lane >> 2;
    const int l4   = lane & 3;
    const int wm   = (wid & 1) * 64;
    const int wn   = (wid >> 1) * 32;
    const int bm   = blockIdx.y * 128;
    const int bn   = blockIdx.x * 128;

    const uint32_t as_sm = (uint32_t)__cvta_generic_to_shared(As);
    const uint32_t bs_sm = (uint32_t)__cvta_generic_to_shared(Bs);

    // per-thread copy coords: 2 A chunks, 2 B chunks per tile
    const int ar0 = t >> 2,  aq0 = (t & 3) << 2;          // A chunk 0: row, col4
    const int ar1 = (t + 256) >> 2, aq1 = aq0;            // A chunk 1
    const int br0 = t >> 5,  bq0 = (t & 31) << 2;         // B chunk 0
    const int br1 = ((t + 256) >> 5), bq1 = bq0;          // B chunk 1 (row+8)

    auto issue = [&](int st, int kt) {
        const float* ap = A + (size_t)bm * K + kt * 16;
        const float* bp = Bm + (size_t)(kt * 16) * N + bn;
        uint32_t ab = as_sm + st * GA_ST * 4;
        uint32_t bb = bs_sm + st * GB_ST * 4;
        cp16(ab + (ar0 * 20 + aq0) * 4, ap + (size_t)ar0 * K + aq0);
        cp16(ab + (ar1 * 20 + aq1) * 4, ap + (size_t)ar1 * K + aq1);
        cp16(bb + (br0 * 136 + bq0) * 4, bp + (size_t)br0 * N + bq0);
        cp16(bb + (br1 * 136 + bq1) * 4, bp + (size_t)br1 * N + bq1);
        cp_commit();
    };

    float acc[4][4][4];
#pragma unroll
    for (int mt = 0; mt < 4; mt++)
#pragma unroll
        for (int nt = 0; nt < 4; nt++)
#pragma unroll
            for (int e = 0; e < 4; e++) acc[mt][nt][e] = 0.f;

    const int nk = K >> 4;
    issue(0, 0);

    for (int kt = 0; kt < nk; kt++) {
        cp_wait<0>();
        __syncthreads();
        if (kt + 1 < nk) issue((kt + 1) & 1, kt + 1);

        const uint32_t* Ac = As + (kt & 1) * GA_ST;
        const uint32_t* Bc = Bs + (kt & 1) * GB_ST;

#pragma unroll
        for (int ks = 0; ks < 2; ks++) {
            const int k0 = ks * 8;
            uint32_t af[4][4], bf[4][2];
#pragma unroll
            for (int mt = 0; mt < 4; mt++) {
                const int rb = (wm + mt * 16 + g) * 20 + k0 + l4;
                af[mt][0] = Ac[rb];
                af[mt][1] = Ac[rb + 8 * 20];
                af[mt][2] = Ac[rb + 4];
                af[mt][3] = Ac[rb + 8 * 20 + 4];
            }
#pragma unroll
            for (int nt = 0; nt < 4; nt++) {
                const int rb = (k0 + l4) * 136 + wn + nt * 8 + g;
                bf[nt][0] = Bc[rb];
                bf[nt][1] = Bc[rb + 4 * 136];
            }
#pragma unroll
            for (int mt = 0; mt < 4; mt++)
#pragma unroll
                for (int nt = 0; nt < 4; nt++)
                    mma8(acc[mt][nt], af[mt][0], af[mt][1], af[mt][2], af[mt][3],
                         bf[nt][0], bf[nt][1]);
        }
        __syncthreads();
    }

#pragma unroll
    for (int mt = 0; mt < 4; mt++) {
#pragma unroll
        for (int nt = 0; nt < 4; nt++) {
            const int row = bm + wm + mt * 16 + g;
            const int col = bn + wn + nt * 8 + l4 * 2;
            float b0 = bias ? bias[col]     : 0.f;
            float b1 = bias ? bias[col + 1] : 0.f;
            *(float2*)(C + (size_t)row * N + col) =
                make_float2(acc[mt][nt][0] + b0, acc[mt][nt][1] + b1);
            *(float2*)(C + (size_t)(row + 8) * N + col) =
                make_float2(acc[mt][nt][2] + b0, acc[mt][nt][3] + b1);
        }
    }
}

// ---------------------------------------------------------------------------
// RoPE + scatter: qkv[4096,6144] -> q,k,v in [B,H,S,HD], tf32-rounded.
// ---------------------------------------------------------------------------
__global__ void rope_kernel(const float* __restrict__ qkv,
                            const float* __restrict__ cosb,
                            const float* __restrict__ sinb,
                            float* __restrict__ q, float* __restrict__ k,
                            float* __restrict__ v) {
    const int idx = blockIdx.x * blockDim.x + threadIdx.x;
    const int d = idx & 127;
    const int h = (idx >> 7) & 15;
    const int s = (idx >> 11) & 2047;
    const int b = idx >> 22;

    const float* row = qkv + (size_t)(b * S_ + s) * N3_;
    const float c  = cosb[s * HD_ + d];
    const float sn = sinb[s * HD_ + d];
    const int col   = h * HD_ + d;
    const int paird = (d < 64) ? d + 64 : d - 64;
    const float sgn = (d < 64) ? -1.f : 1.f;

    const float qv = row[col];
    const float qp = row[h * HD_ + paird];
    const float kv = row[DM_ + col];
    const float kp = row[DM_ + h * HD_ + paird];

    const size_t o = ((size_t)((b * H_ + h) * S_ + s)) * HD_ + d;
    ((uint32_t*)q)[o] = f2tf(fmaf(qv, c, sgn * qp * sn));
    ((uint32_t*)k)[o] = f2tf(fmaf(kv, c, sgn * kp * sn));
    ((uint32_t*)v)[o] = f2tf(row[2 * DM_ + col]);
}

// ---------------------------------------------------------------------------
// Causal flash attention, tf32 mma, cp.async double-buffered K/V.
// Block: 128 q-rows x one (b,h). 256 threads = 8 warps; warp owns 16 q-rows.
// Q fragments live in registers (loaded once via LDG from pre-rounded g_q).
// Smem: Kst[2][64][136], Vst[2][64][136] (raw [j][d] + pad), Ps[64][136].
// Fragment patterns verified bank-conflict-free with pitch 136.
// ---------------------------------------------------------------------------
static constexpr int FL_ST  = 64 * 136;                // 8704 u32 per stage
static constexpr int KS0_O = 0;
static constexpr int KS1_O = FL_ST;
static constexpr int VS0_O = 2 * FL_ST;
static constexpr int VS1_O = 3 * FL_ST;
static constexpr int PS_O  = 4 * FL_ST;
static constexpr int FL_SMEM_BYTES = 5 * FL_ST * 4;    // 174080

__global__ __launch_bounds__(256, 1)
void flash_tf32(const float* __restrict__ Q, const float* __restrict__ K,
                const float* __restrict__ V, float* __restrict__ Ctx) {
    extern __shared__ uint32_t sm[];
    const int t    = threadIdx.x;
    const int lane = t & 31;
    const int wid  = t >> 5;
    const int g    = lane >> 2;
    const int l4   = lane & 3;
    const int mrow = wid * 16;

    const int bid = blockIdx.x;
    const int qt  = ((int)gridDim.x >> 5) - 1 - (bid >> 5);  // heavy tiles first
    const int bh  = bid & 31;
    const int q0  = qt * 128;

    const float* Qp = Q + (size_t)bh * S_ * HD_;
    const float* Kp = K + (size_t)bh * S_ * HD_;
    const float* Vp = V + (size_t)bh * S_ * HD_;

    const uint32_t smb = (uint32_t)__cvta_generic_to_shared(sm);

    auto issue = [&](int st, int kt) {
        const float* kp = Kp + (size_t)(kt * 64) * HD_;
        const float* vp = Vp + (size_t)(kt * 64) * HD_;
        const uint32_t kb = smb + (st ? KS1_O : KS0_O) * 4;
        const uint32_t vb = smb + (st ? VS1_O : VS0_O) * 4;
#pragma unroll
        for (int i = 0; i < 8; i++) {
            const int c = t + 256 * i;
            const int j = c >> 5;
            const int q = (c & 31) << 2;
            cp16(kb + (j * 136 + q) * 4, kp + (size_t)j * HD_ + q);
            cp16(vb + (j * 136 + q) * 4, vp + (size_t)j * HD_ + q);
        }
        cp_commit();
    };

    issue(0, 0);

    // Q fragments in registers: qf[ks][0..3] for ks = 0..15 (K dim 128)
    uint32_t qf[16][4];
    {
        const int r0 = q0 + mrow + g;
        const uint32_t* q0p = (const uint32_t*)(Qp + (size_t)r0 * HD_);
        const uint32_t* q1p = (const uint32_t*)(Qp + (size_t)(r0 + 8) * HD_);
#pragma unroll
        for (int ks = 0; ks < 16; ks++) {
            const int c = ks * 8 + l4;
            qf[ks][0] = q0p[c];
            qf[ks][1] = q1p[c];
            qf[ks][2] = q0p[c + 4];
            qf[ks][3] = q1p[c + 4];
        }
    }

    float o[16][4];
#pragma unroll
    for (int nt = 0; nt < 16; nt++)
#pragma unroll
        for (int e = 0; e < 4; e++) o[nt][e] = 0.f;
    float m0 = -1e30f, m1 = -1e30f, li0 = 0.f, li1 = 0.f;
    const float scale = 0.08838834764831845f;   // 1/sqrt(128)

    uint32_t* Ps = sm + PS_O;
    const int nkt = 2 * qt + 2;

    for (int kt = 0; kt < nkt; kt++) {
        cp_wait<0>();
        __syncthreads();               // stage ready; prior PV done with bufs
        if (kt + 1 < nkt) issue((kt + 1) & 1, kt + 1);

        const uint32_t* Ks = sm + ((kt & 1) ? KS1_O : KS0_O);
        const uint32_t* Vs = sm + ((kt & 1) ? VS1_O : VS0_O);
        const int k0g = kt * 64;

        // S = Q K^T : warp rows [mrow,mrow+16) x 64 cols
        float sc[8][4];
#pragma unroll
        for (int nt = 0; nt < 8; nt++)
#pragma unroll
            for (int e = 0; e < 4; e++) sc[nt][e] = 0.f;

#pragma unroll
        for (int ks = 0; ks < 16; ks++) {
            const int k0 = ks * 8;
            const uint32_t a0 = qf[ks][0], a1 = qf[ks][1];
            const uint32_t a2 = qf[ks][2], a3 = qf[ks][3];
#pragma unroll
            for (int nt = 0; nt < 8; nt++) {
                const int rb = (nt * 8 + g) * 136 + k0 + l4;
                mma8(sc[nt], a0, a1, a2, a3, Ks[rb], Ks[rb + 4]);
            }
        }

        // scale + causal mask
        const bool need_mask = (kt >= 2 * qt);
        const int row0 = q0 + mrow + g;
        const int row1 = row0 + 8;
#pragma unroll
        for (int nt = 0; nt < 8; nt++) {
            const int col = k0g + nt * 8 + l4 * 2;
#pragma unroll
            for (int e = 0; e < 4; e++) sc[nt][e] *= scale;
            if (need_mask) {
                if (col     > row0) sc[nt][0] = -1e30f;
                if (col + 1 > row0) sc[nt][1] = -1e30f;
                if (col     > row1) sc[nt][2] = -1e30f;
                if (col + 1 > row1) sc[nt][3] = -1e30f;
            }
        }

        // online softmax
        float rm0 = -1e30f, rm1 = -1e30f;
#pragma unroll
        for (int nt = 0; nt < 8; nt++) {
            rm0 = fmaxf(rm0, fmaxf(sc[nt][0], sc[nt][1]));
            rm1 = fmaxf(rm1, fmaxf(sc[nt][2], sc[nt][3]));
        }
        rm0 = fmaxf(rm0, __shfl_xor_sync(0xffffffffu, rm0, 1));
        rm0 = fmaxf(rm0, __shfl_xor_sync(0xffffffffu, rm0, 2));
        rm1 = fmaxf(rm1, __shfl_xor_sync(0xffffffffu, rm1, 1));
        rm1 = fmaxf(rm1, __shfl_xor_sync(0xffffffffu, rm1, 2));

        const float mn0 = fmaxf(m0, rm0), mn1 = fmaxf(m1, rm1);
        const float corr0 = __expf(m0 - mn0), corr1 = __expf(m1 - mn1);
        float rs0 = 0.f, rs1 = 0.f;
#pragma unroll
        for (int nt = 0; nt < 8; nt++) {
            sc[nt][0] = __expf(sc[nt][0] - mn0);
            sc[nt][1] = __expf(sc[nt][1] - mn0);
            sc[nt][2] = __expf(sc[nt][2] - mn1);
            sc[nt][3] = __expf(sc[nt][3] - mn1);
            rs0 += sc[nt][0] + sc[nt][1];
            rs1 += sc[nt][2] + sc[nt][3];
        }
        rs0 += __shfl_xor_sync(0xffffffffu, rs0, 1);
        rs0 += __shfl_xor_sync(0xffffffffu, rs0, 2);
        rs1 += __shfl_xor_sync(0xffffffffu, rs1, 1);
        rs1 += __shfl_xor_sync(0xffffffffu, rs1, 2);
        li0 = li0 * corr0 + rs0; m0 = mn0;
        li1 = li1 * corr1 + rs1; m1 = mn1;
#pragma unroll
        for (int nt = 0; nt < 16; nt++) {
            o[nt][0] *= corr0; o[nt][1] *= corr0;
            o[nt][2] *= corr1; o[nt][3] *= corr1;
        }

        // write P transposed: Ps[j][m]
#pragma unroll
        for (int nt = 0; nt < 8; nt++) {
            const int cb = nt * 8 + l4 * 2;
            Ps[cb * 136       + mrow + g]     = f2tf(sc[nt][0]);
            Ps[(cb + 1) * 136 + mrow + g]     = f2tf(sc[nt][1]);
            Ps[cb * 136       + mrow + g + 8] = f2tf(sc[nt][2]);
            Ps[(cb + 1) * 136 + mrow + g + 8] = f2tf(sc[nt][3]);
        }
        __syncthreads();

        // O += P V
#pragma unroll
        for (int ks = 0; ks < 8; ks++) {
            const int k0 = ks * 8;
            const int ab = (k0 + l4) * 136 + mrow + g;
            const uint32_t a0 = Ps[ab], a1 = Ps[ab + 8];
            const uint32_t a2 = Ps[ab + 4 * 136], a3 = Ps[ab + 4 * 136 + 8];
#pragma unroll
            for (int nt = 0; nt < 16; nt++) {
                const int rb = (k0 + l4) * 136 + nt * 8 + g;
                mma8(o[nt], a0, a1, a2, a3, Vs[rb], Vs[rb + 4 * 136]);
            }
        }
    }

    // epilogue: normalize, tf32-round (proj consumes raw bytes), write ctx
    const int b = bh >> 4;
    const int h = bh & 15;
    const float inv0 = 1.f / li0, inv1 = 1.f / li1;
    const int r0 = q0 + mrow + g;
#pragma unroll
    for (int nt = 0; nt < 16; nt++) {
        const int col = h * HD_ + nt * 8 + l4 * 2;
        uint32_t* c0 = (uint32_t*)(Ctx + (size_t)(b * S_ + r0) * DM_ + col);
        uint32_t* c1 = (uint32_t*)(Ctx + (size_t)(b * S_ + r0 + 8) * DM_ + col);
        *(uint2*)c0 = make_uint2(f2tf(o[nt][0] * inv0), f2tf(o[nt][1] * inv0));
        *(uint2*)c1 = make_uint2(f2tf(o[nt][2] * inv1), f2tf(o[nt][3] * inv1));
    }
}

// ---------------------------------------------------------------------------
// Launch orchestration
// ---------------------------------------------------------------------------
extern "C" void kernel_launch(void* const* d_in, const int* in_sizes, int n_in,
                              void* d_out, int out_size) {
    const float* hs     = (const float*)d_in[0];
    const float* cosb   = (const float*)d_in[1];
    const float* sinb   = (const float*)d_in[2];
    const float* w_attn = (const float*)d_in[3];
    const float* b_attn = (const float*)d_in[4];
    const float* w_proj = (const float*)d_in[5];
    float* out = (float*)d_out;

    float *qkv, *q, *k, *v, *ctx, *hsr, *war, *wpr;
    cudaGetSymbolAddress((void**)&qkv, g_qkv);
    cudaGetSymbolAddress((void**)&q,   g_q);
    cudaGetSymbolAddress((void**)&k,   g_k);
    cudaGetSymbolAddress((void**)&v,   g_v);
    cudaGetSymbolAddress((void**)&ctx, g_ctx);
    cudaGetSymbolAddress((void**)&hsr, g_hsr);
    cudaGetSymbolAddress((void**)&war, g_war);
    cudaGetSymbolAddress((void**)&wpr, g_wpr);

    // 0) pre-round operands to tf32
    {
        int n4;
        n4 = (M_ * DM_) / 4;
        round4_kernel<<<(n4 + 255) / 256, 256>>>(hs, hsr, n4);
        n4 = (DM_ * N3_) / 4;
        round4_kernel<<<(n4 + 255) / 256, 256>>>(w_attn, war, n4);
        n4 = (DM_ * DM_) / 4;
        round4_kernel<<<(n4 + 255) / 256, 256>>>(w_proj, wpr, n4);
    }
    // 1) QKV GEMM + bias
    {
        dim3 grid(N3_ / 128, M_ / 128);
        gemm_tf32<<<grid, 256>>>(hsr, war, b_attn, qkv, M_, N3_, DM_);
    }
    // 2) RoPE + scatter (tf32-rounded outputs)
    {
        const int total = B_ * S_ * H_ * HD_;
        rope_kernel<<<total / 256, 256>>>(qkv, cosb, sinb, q, k, v);
    }
    // 3) Causal flash attention
    {
        cudaFuncSetAttribute(flash_tf32,
                             cudaFuncAttributeMaxDynamicSharedMemorySize,
                             FL_SMEM_BYTES);
        flash_tf32<<<(S_ / 128) * B_ * H_, 256, FL_SMEM_BYTES>>>(q, k, v, ctx);
    }
    // 4) Projection GEMM
    {
        dim3 grid(DM_ / 128, M_ / 128);
        gemm_tf32<<<grid, 256>>>(ctx, wpr, nullptr, out, M_, DM_, DM_);
    }
}

// round 5
// speedup vs baseline: 2.7861x; 1.0063x over previous
#include <cuda_runtime.h>
#include <cstdint>

// Problem constants: B=2, S=2048, DM=2048, H=16, HD=128
static constexpr int B_   = 2;
static constexpr int S_   = 2048;
static constexpr int DM_  = 2048;
static constexpr int H_   = 16;
static constexpr int HD_  = 128;
static constexpr int M_   = B_ * S_;        // 4096
static constexpr int N3_  = 3 * DM_;        // 6144

// ---------------------------------------------------------------------------
// Scratch (no allocations allowed -> __device__ globals)
// ---------------------------------------------------------------------------
__device__ float g_qkv[(size_t)M_ * N3_];              // [4096, 6144] fp32
__device__ float g_q  [(size_t)B_ * H_ * S_ * HD_];    // [bh][s][d] tf32
__device__ float g_k  [(size_t)B_ * H_ * S_ * HD_];    // [bh][s][d] tf32
__device__ float g_vt [(size_t)B_ * H_ * S_ * HD_];    // [bh][d][s] tf32 (V^T)
__device__ float g_ctx[(size_t)M_ * DM_];              // [B,S,DM] tf32-rounded
__device__ float g_hsr[(size_t)M_ * DM_];              // tf32-rounded hs
__device__ float g_war[(size_t)DM_ * N3_];             // tf32-rounded w_attn
__device__ float g_wpr[(size_t)DM_ * DM_];             // tf32-rounded w_proj

// ---------------------------------------------------------------------------
// helpers
// ---------------------------------------------------------------------------
__device__ __forceinline__ uint32_t f2tf(float x) {
    uint32_t u;
    asm("cvt.rna.tf32.f32 %0, %1;" : "=r"(u) : "f"(x));
    return u;
}

__device__ __forceinline__ void mma8(float* c,
                                     uint32_t a0, uint32_t a1, uint32_t a2, uint32_t a3,
                                     uint32_t b0, uint32_t b1) {
    asm volatile(
        "mma.sync.aligned.m16n8k8.row.col.f32.tf32.tf32.f32 "
        "{%0,%1,%2,%3},{%4,%5,%6,%7},{%8,%9},{%0,%1,%2,%3};"
        : "+f"(c[0]), "+f"(c[1]), "+f"(c[2]), "+f"(c[3])
        : "r"(a0), "r"(a1), "r"(a2), "r"(a3), "r"(b0), "r"(b1));
}

__device__ __forceinline__ void ldsm4(uint32_t& r0, uint32_t& r1,
                                      uint32_t& r2, uint32_t& r3, uint32_t addr) {
    asm volatile("ldmatrix.sync.aligned.m8n8.x4.shared.b16 {%0,%1,%2,%3}, [%4];"
                 : "=r"(r0), "=r"(r1), "=r"(r2), "=r"(r3) : "r"(addr));
}

__device__ __forceinline__ void cp16(uint32_t dst_smem, const void* src) {
    asm volatile("cp.async.cg.shared.global [%0], [%1], 16;"
                 :: "r"(dst_smem), "l"(src));
}
__device__ __forceinline__ void cp_commit() {
    asm volatile("cp.async.commit_group;");
}
template <int N>
__device__ __forceinline__ void cp_wait() {
    asm volatile("cp.async.wait_group %0;" :: "n"(N));
}

// ---------------------------------------------------------------------------
// Prep: round fp32 arrays to tf32 (rna)
// ---------------------------------------------------------------------------
__global__ void round4_kernel(const float* __restrict__ in,
                              float* __restrict__ out, int n4) {
    int i = blockIdx.x * blockDim.x + threadIdx.x;
    if (i >= n4) return;
    float4 v = ((const float4*)in)[i];
    ((uint4*)out)[i] = make_uint4(f2tf(v.x), f2tf(v.y), f2tf(v.z), f2tf(v.w));
}

// ---------------------------------------------------------------------------
// tf32 GEMM, cp.async double-buffered, a-frags via ldmatrix.
// As[m=128][k=16] pitch 20, Bs[k=16][n=128] pitch 136.
// ---------------------------------------------------------------------------
static constexpr int GA_ST = 128 * 20;   // 2560 u32 per A stage
static constexpr int GB_ST = 16 * 136;   // 2176 u32 per B stage

__global__ __launch_bounds__(256, 1)
void gemm_tf32(const float* __restrict__ A, const float* __restrict__ Bm,
               const float* __restrict__ bias, float* __restrict__ C,
               int M, int N, int K) {
    __shared__ uint32_t As[2 * GA_ST];
    __shared__ uint32_t Bs[2 * GB_ST];

    const int t    = threadIdx.x;
    const int lane = t & 31;
    const int wid  = t >> 5;
    const int g    = lane >> 2;
    const int l4   = lane & 3;
    const int lrow = lane & 7;          // ldsm row within matrix
    const int lsel = lane >> 3;         // ldsm matrix index 0..3
    const int wm   = (wid & 1) * 64;
    const int wn   = (wid >> 1) * 32;
    const int bm   = blockIdx.y * 128;
    const int bn   = blockIdx.x * 128;

    const uint32_t as_sm = (uint32_t)__cvta_generic_to_shared(As);
    const uint32_t bs_sm = (uint32_t)__cvta_generic_to_shared(Bs);

    const int ar0 = t >> 2,  aq0 = (t & 3) << 2;
    const int ar1 = (t + 256) >> 2;
    const int br0 = t >> 5,  bq0 = (t & 31) << 2;
    const int br1 = ((t + 256) >> 5);

    auto issue = [&](int st, int kt) {
        const float* ap = A + (size_t)bm * K + kt * 16;
        const float* bp = Bm + (size_t)(kt * 16) * N + bn;
        uint32_t ab = as_sm + st * GA_ST * 4;
        uint32_t bb = bs_sm + st * GB_ST * 4;
        cp16(ab + (ar0 * 20 + aq0) * 4, ap + (size_t)ar0 * K + aq0);
        cp16(ab + (ar1 * 20 + aq0) * 4, ap + (size_t)ar1 * K + aq0);
        cp16(bb + (br0 * 136 + bq0) * 4, bp + (size_t)br0 * N + bq0);
        cp16(bb + (br1 * 136 + bq0) * 4, bp + (size_t)br1 * N + bq0);
        cp_commit();
    };

    float acc[4][4][4];
#pragma unroll
    for (int mt = 0; mt < 4; mt++)
#pragma unroll
        for (int nt = 0; nt < 4; nt++)
#pragma unroll
            for (int e = 0; e < 4; e++) acc[mt][nt][e] = 0.f;

    const int nk = K >> 4;
    issue(0, 0);

    const uint32_t a_lane = (uint32_t)((lrow + 8 * (lsel & 1)) * 20 + 4 * (lsel >> 1)) * 4;

    for (int kt = 0; kt < nk; kt++) {
        cp_wait<0>();
        __syncthreads();
        if (kt + 1 < nk) issue((kt + 1) & 1, kt + 1);

        const uint32_t a_st = as_sm + (kt & 1) * GA_ST * 4;
        const uint32_t* Bc  = Bs + (kt & 1) * GB_ST;

#pragma unroll
        for (int ks = 0; ks < 2; ks++) {
            const int k0 = ks * 8;
            uint32_t af[4][4], bf[4][2];
#pragma unroll
            for (int mt = 0; mt < 4; mt++)
                ldsm4(af[mt][0], af[mt][1], af[mt][2], af[mt][3],
                      a_st + a_lane + (uint32_t)((wm + mt * 16) * 20 + k0) * 4);
#pragma unroll
            for (int nt = 0; nt < 4; nt++) {
                const int rb = (k0 + l4) * 136 + wn + nt * 8 + g;
                bf[nt][0] = Bc[rb];
                bf[nt][1] = Bc[rb + 4 * 136];
            }
#pragma unroll
            for (int mt = 0; mt < 4; mt++)
#pragma unroll
                for (int nt = 0; nt < 4; nt++)
                    mma8(acc[mt][nt], af[mt][0], af[mt][1], af[mt][2], af[mt][3],
                         bf[nt][0], bf[nt][1]);
        }
        __syncthreads();
    }

#pragma unroll
    for (int mt = 0; mt < 4; mt++) {
#pragma unroll
        for (int nt = 0; nt < 4; nt++) {
            const int row = bm + wm + mt * 16 + g;
            const int col = bn + wn + nt * 8 + l4 * 2;
            float b0 = bias ? bias[col]     : 0.f;
            float b1 = bias ? bias[col + 1] : 0.f;
            *(float2*)(C + (size_t)row * N + col) =
                make_float2(acc[mt][nt][0] + b0, acc[mt][nt][1] + b1);
            *(float2*)(C + (size_t)(row + 8) * N + col) =
                make_float2(acc[mt][nt][2] + b0, acc[mt][nt][3] + b1);
        }
    }
}

// ---------------------------------------------------------------------------
// RoPE + scatter for Q,K only: qkv -> q,k in [bh][s][d], tf32-rounded.
// ---------------------------------------------------------------------------
__global__ void rope_kernel(const float* __restrict__ qkv,
                            const float* __restrict__ cosb,
                            const float* __restrict__ sinb,
                            float* __restrict__ q, float* __restrict__ k) {
    const int idx = blockIdx.x * blockDim.x + threadIdx.x;
    const int d = idx & 127;
    const int h = (idx >> 7) & 15;
    const int s = (idx >> 11) & 2047;
    const int b = idx >> 22;

    const float* row = qkv + (size_t)(b * S_ + s) * N3_;
    const float c  = cosb[s * HD_ + d];
    const float sn = sinb[s * HD_ + d];
    const int col   = h * HD_ + d;
    const int paird = (d < 64) ? d + 64 : d - 64;
    const float sgn = (d < 64) ? -1.f : 1.f;

    const float qv = row[col];
    const float qp = row[h * HD_ + paird];
    const float kv = row[DM_ + col];
    const float kp = row[DM_ + h * HD_ + paird];

    const size_t o = ((size_t)((b * H_ + h) * S_ + s)) * HD_ + d;
    ((uint32_t*)q)[o] = f2tf(fmaf(qv, c, sgn * qp * sn));
    ((uint32_t*)k)[o] = f2tf(fmaf(kv, c, sgn * kp * sn));
}

// ---------------------------------------------------------------------------
// V transpose: qkv v-columns -> g_vt[bh][d][s], tf32-rounded. 32x32 tiles.
// ---------------------------------------------------------------------------
__global__ void vtrans_kernel(const float* __restrict__ qkv,
                              float* __restrict__ vt) {
    __shared__ float tile[32][33];
    const int s0 = blockIdx.x * 32;
    const int d0 = blockIdx.y * 32;
    const int bh = blockIdx.z;
    const int b = bh >> 4, h = bh & 15;
    const int tx = threadIdx.x, ty = threadIdx.y;

    const float* src = qkv + (size_t)(b * S_ + s0) * N3_ + 2 * DM_ + h * HD_ + d0;
#pragma unroll
    for (int i = 0; i < 4; i++) {
        const int r = ty + i * 8;                     // s-local
        tile[r][tx] = src[(size_t)r * N3_ + tx];
    }
    __syncthreads();
    float* dst = vt + ((size_t)bh * HD_ + d0) * S_ + s0;
#pragma unroll
    for (int i = 0; i < 4; i++) {
        const int r = ty + i * 8;                     // d-local
        ((uint32_t*)dst)[(size_t)r * S_ + tx] = f2tf(tile[tx][r]);
    }
}

// ---------------------------------------------------------------------------
// Causal flash attention, tf32 mma, ldmatrix fragments, cp.async K/V.
// Block: 128 q-rows x (b,h). 256 threads = 8 warps (16 q-rows each).
// Smem: K[2][64][132] ([j][d]), Vt[2][128][68] ([d][j]), Ps[128][68] ([m][j]).
// ---------------------------------------------------------------------------
static constexpr int K_ST   = 64 * 132;               // 8448
static constexpr int VT_ST  = 128 * 68;               // 8704
static constexpr int KS0_O  = 0;
static constexpr int KS1_O  = K_ST;
static constexpr int VT0_O  = 2 * K_ST;
static constexpr int VT1_O  = 2 * K_ST + VT_ST;
static constexpr int PS_O   = 2 * K_ST + 2 * VT_ST;
static constexpr int FL_SMEM_BYTES = (PS_O + 128 * 68) * 4;   // 172032

__global__ __launch_bounds__(256, 1)
void flash_tf32(const float* __restrict__ Q, const float* __restrict__ K,
                const float* __restrict__ Vt, float* __restrict__ Ctx) {
    extern __shared__ uint32_t sm[];
    const int t    = threadIdx.x;
    const int lane = t & 31;
    const int wid  = t >> 5;
    const int g    = lane >> 2;
    const int l4   = lane & 3;
    const int lrow = lane & 7;
    const int lsel = lane >> 3;
    const int mrow = wid * 16;

    const int bid = blockIdx.x;
    const int qt  = ((int)gridDim.x >> 5) - 1 - (bid >> 5);  // heavy first
    const int bh  = bid & 31;
    const int q0  = qt * 128;

    const float* Qp  = Q  + (size_t)bh * S_ * HD_;
    const float* Kp  = K  + (size_t)bh * S_ * HD_;
    const float* Vtp = Vt + (size_t)bh * HD_ * S_;    // [d][s]

    const uint32_t smb = (uint32_t)__cvta_generic_to_shared(sm);

    auto issue = [&](int st, int kt) {
        const float* kp = Kp + (size_t)(kt * 64) * HD_;
        const uint32_t kb = smb + (st ? KS1_O : KS0_O) * 4;
        const uint32_t vb = smb + (st ? VT1_O : VT0_O) * 4;
        const int vcol = kt * 64;
#pragma unroll
        for (int i = 0; i < 8; i++) {
            const int c = t + 256 * i;
            const int kj = c >> 5, kq = (c & 31) << 2;
            cp16(kb + (kj * 132 + kq) * 4, kp + (size_t)kj * HD_ + kq);
            const int vd = c >> 4, vq = (c & 15) << 2;
            cp16(vb + (vd * 68 + vq) * 4, Vtp + (size_t)vd * S_ + vcol + vq);
        }
        cp_commit();
    };

    issue(0, 0);

    // Q fragments in registers
    uint32_t qf[16][4];
    {
        const int r0 = q0 + mrow + g;
        const uint32_t* q0p = (const uint32_t*)(Qp + (size_t)r0 * HD_);
        const uint32_t* q1p = (const uint32_t*)(Qp + (size_t)(r0 + 8) * HD_);
#pragma unroll
        for (int ks = 0; ks < 16; ks++) {
            const int c = ks * 8 + l4;
            qf[ks][0] = q0p[c];
            qf[ks][1] = q1p[c];
            qf[ks][2] = q0p[c + 4];
            qf[ks][3] = q1p[c + 4];
        }
    }

    float o[16][4];
#pragma unroll
    for (int nt = 0; nt < 16; nt++)
#pragma unroll
        for (int e = 0; e < 4; e++) o[nt][e] = 0.f;
    float m0 = -1e30f, m1 = -1e30f, li0 = 0.f, li1 = 0.f;
    const float scale = 0.08838834764831845f;

    const uint32_t kb_lane = (uint32_t)(lrow * 132 + 4 * lsel) * 4;
    const uint32_t vb_lane = (uint32_t)(lrow * 68 + 4 * lsel) * 4;
    const uint32_t pa_lane = (uint32_t)((mrow + lrow + 8 * (lsel & 1)) * 68 +
                                        4 * (lsel >> 1)) * 4;
    const uint32_t ps_byte = smb + PS_O * 4;

    const int nkt = 2 * qt + 2;
    for (int kt = 0; kt < nkt; kt++) {
        cp_wait<0>();
        __syncthreads();
        if (kt + 1 < nkt) issue((kt + 1) & 1, kt + 1);

        const uint32_t ks_b = smb + ((kt & 1) ? KS1_O : KS0_O) * 4;
        const uint32_t vt_b = smb + ((kt & 1) ? VT1_O : VT0_O) * 4;
        const int k0g = kt * 64;

        // ---- S = Q K^T ----
        float sc[8][4];
#pragma unroll
        for (int nt = 0; nt < 8; nt++)
#pragma unroll
            for (int e = 0; e < 4; e++) sc[nt][e] = 0.f;

#pragma unroll
        for (int p = 0; p < 8; p++) {
            const uint32_t colb = (uint32_t)(16 * p) * 4;
#pragma unroll
            for (int nt = 0; nt < 8; nt++) {
                uint32_t b0, b1, b2, b3;
                ldsm4(b0, b1, b2, b3,
                      ks_b + kb_lane + (uint32_t)(nt * 8 * 132) * 4 + colb);
                mma8(sc[nt], qf[2*p][0], qf[2*p][1], qf[2*p][2], qf[2*p][3], b0, b1);
                mma8(sc[nt], qf[2*p+1][0], qf[2*p+1][1], qf[2*p+1][2], qf[2*p+1][3], b2, b3);
            }
        }

        // ---- scale + causal mask ----
        const bool need_mask = (kt >= 2 * qt);
        const int row0 = q0 + mrow + g;
        const int row1 = row0 + 8;
#pragma unroll
        for (int nt = 0; nt < 8; nt++) {
            const int col = k0g + nt * 8 + l4 * 2;
#pragma unroll
            for (int e = 0; e < 4; e++) sc[nt][e] *= scale;
            if (need_mask) {
                if (col     > row0) sc[nt][0] = -1e30f;
                if (col + 1 > row0) sc[nt][1] = -1e30f;
                if (col     > row1) sc[nt][2] = -1e30f;
                if (col + 1 > row1) sc[nt][3] = -1e30f;
            }
        }

        // ---- online softmax ----
        float rm0 = -1e30f, rm1 = -1e30f;
#pragma unroll
        for (int nt = 0; nt < 8; nt++) {
            rm0 = fmaxf(rm0, fmaxf(sc[nt][0], sc[nt][1]));
            rm1 = fmaxf(rm1, fmaxf(sc[nt][2], sc[nt][3]));
        }
        rm0 = fmaxf(rm0, __shfl_xor_sync(0xffffffffu, rm0, 1));
        rm0 = fmaxf(rm0, __shfl_xor_sync(0xffffffffu, rm0, 2));
        rm1 = fmaxf(rm1, __shfl_xor_sync(0xffffffffu, rm1, 1));
        rm1 = fmaxf(rm1, __shfl_xor_sync(0xffffffffu, rm1, 2));

        const float mn0 = fmaxf(m0, rm0), mn1 = fmaxf(m1, rm1);
        const float corr0 = __expf(m0 - mn0), corr1 = __expf(m1 - mn1);
        float rs0 = 0.f, rs1 = 0.f;
#pragma unroll
        for (int nt = 0; nt < 8; nt++) {
            sc[nt][0] = __expf(sc[nt][0] - mn0);
            sc[nt][1] = __expf(sc[nt][1] - mn0);
            sc[nt][2] = __expf(sc[nt][2] - mn1);
            sc[nt][3] = __expf(sc[nt][3] - mn1);
            rs0 += sc[nt][0] + sc[nt][1];
            rs1 += sc[nt][2] + sc[nt][3];
        }
        rs0 += __shfl_xor_sync(0xffffffffu, rs0, 1);
        rs0 += __shfl_xor_sync(0xffffffffu, rs0, 2);
        rs1 += __shfl_xor_sync(0xffffffffu, rs1, 1);
        rs1 += __shfl_xor_sync(0xffffffffu, rs1, 2);
        li0 = li0 * corr0 + rs0; m0 = mn0;
        li1 = li1 * corr1 + rs1; m1 = mn1;
#pragma unroll
        for (int nt = 0; nt < 16; nt++) {
            o[nt][0] *= corr0; o[nt][1] *= corr0;
            o[nt][2] *= corr1; o[nt][3] *= corr1;
        }

        // ---- write P to Ps[m][j] (tf32), STS.64 ----
        {
            uint32_t* Ps = sm + PS_O;
#pragma unroll
            for (int nt = 0; nt < 8; nt++) {
                const int cb = nt * 8 + l4 * 2;
                *(uint2*)(&Ps[(mrow + g) * 68 + cb]) =
                    make_uint2(f2tf(sc[nt][0]), f2tf(sc[nt][1]));
                *(uint2*)(&Ps[(mrow + g + 8) * 68 + cb]) =
                    make_uint2(f2tf(sc[nt][2]), f2tf(sc[nt][3]));
            }
        }
        __syncthreads();

        // ---- O += P V ----
#pragma unroll
        for (int p = 0; p < 4; p++) {
            uint32_t pa0[4], pa1[4];
            ldsm4(pa0[0], pa0[1], pa0[2], pa0[3],
                  ps_byte + pa_lane + (uint32_t)((2*p) * 8) * 4);
            ldsm4(pa1[0], pa1[1], pa1[2], pa1[3],
                  ps_byte + pa_lane + (uint32_t)((2*p+1) * 8) * 4);
            const uint32_t colb = (uint32_t)(16 * p) * 4;
#pragma unroll
            for (int nt = 0; nt < 16; nt++) {
                uint32_t b0, b1, b2, b3;
                ldsm4(b0, b1, b2, b3,
                      vt_b + vb_lane + (uint32_t)(nt * 8 * 68) * 4 + colb);
                mma8(o[nt], pa0[0], pa0[1], pa0[2], pa0[3], b0, b1);
                mma8(o[nt], pa1[0], pa1[1], pa1[2], pa1[3], b2, b3);
            }
        }
    }

    // epilogue
    const int b = bh >> 4;
    const int h = bh & 15;
    const float inv0 = 1.f / li0, inv1 = 1.f / li1;
    const int r0 = q0 + mrow + g;
#pragma unroll
    for (int nt = 0; nt < 16; nt++) {
        const int col = h * HD_ + nt * 8 + l4 * 2;
        uint32_t* c0 = (uint32_t*)(Ctx + (size_t)(b * S_ + r0) * DM_ + col);
        uint32_t* c1 = (uint32_t*)(Ctx + (size_t)(b * S_ + r0 + 8) * DM_ + col);
        *(uint2*)c0 = make_uint2(f2tf(o[nt][0] * inv0), f2tf(o[nt][1] * inv0));
        *(uint2*)c1 = make_uint2(f2tf(o[nt][2] * inv1), f2tf(o[nt][3] * inv1));
    }
}

// ---------------------------------------------------------------------------
// Launch orchestration
// ---------------------------------------------------------------------------
extern "C" void kernel_launch(void* const* d_in, const int* in_sizes, int n_in,
                              void* d_out, int out_size) {
    const float* hs     = (const float*)d_in[0];
    const float* cosb   = (const float*)d_in[1];
    const float* sinb   = (const float*)d_in[2];
    const float* w_attn = (const float*)d_in[3];
    const float* b_attn = (const float*)d_in[4];
    const float* w_proj = (const float*)d_in[5];
    float* out = (float*)d_out;

    float *qkv, *q, *k, *vt, *ctx, *hsr, *war, *wpr;
    cudaGetSymbolAddress((void**)&qkv, g_qkv);
    cudaGetSymbolAddress((void**)&q,   g_q);
    cudaGetSymbolAddress((void**)&k,   g_k);
    cudaGetSymbolAddress((void**)&vt,  g_vt);
    cudaGetSymbolAddress((void**)&ctx, g_ctx);
    cudaGetSymbolAddress((void**)&hsr, g_hsr);
    cudaGetSymbolAddress((void**)&war, g_war);
    cudaGetSymbolAddress((void**)&wpr, g_wpr);

    // 0) pre-round operands to tf32
    {
        int n4;
        n4 = (M_ * DM_) / 4;
        round4_kernel<<<(n4 + 255) / 256, 256>>>(hs, hsr, n4);
        n4 = (DM_ * N3_) / 4;
        round4_kernel<<<(n4 + 255) / 256, 256>>>(w_attn, war, n4);
        n4 = (DM_ * DM_) / 4;
        round4_kernel<<<(n4 + 255) / 256, 256>>>(w_proj, wpr, n4);
    }
    // 1) QKV GEMM + bias
    {
        dim3 grid(N3_ / 128, M_ / 128);
        gemm_tf32<<<grid, 256>>>(hsr, war, b_attn, qkv, M_, N3_, DM_);
    }
    // 2a) RoPE for Q,K
    {
        const int total = B_ * S_ * H_ * HD_;
        rope_kernel<<<total / 256, 256>>>(qkv, cosb, sinb, q, k);
    }
    // 2b) V transpose to [bh][d][s]
    {
        dim3 grid(S_ / 32, HD_ / 32, B_ * H_);
        vtrans_kernel<<<grid, dim3(32, 8)>>>(qkv, vt);
    }
    // 3) Causal flash attention
    {
        cudaFuncSetAttribute(flash_tf32,
                             cudaFuncAttributeMaxDynamicSharedMemorySize,
                             FL_SMEM_BYTES);
        flash_tf32<<<(S_ / 128) * B_ * H_, 256, FL_SMEM_BYTES>>>(q, k, vt, ctx);
    }
    // 4) Projection GEMM
    {
        dim3 grid(DM_ / 128, M_ / 128);
        gemm_tf32<<<grid, 256>>>(ctx, wpr, nullptr, out, M_, DM_, DM_);
    }
}